// round 5
// baseline (speedup 1.0000x reference)
#include <cuda_runtime.h>

#define WS 8
#define BB 64
#define TT 256
#define HH 64
#define NW 248
#define NP (NW * 8 + 2)   // 1986 phases

typedef unsigned long long u64;

__device__ __forceinline__ void fma2(u64 &acc, u64 a, u64 b) {
    asm("fma.rn.f32x2 %0, %1, %2, %0;" : "+l"(acc) : "l"(a), "l"(b));
}
__device__ __forceinline__ void add2(u64 &a, u64 b) {
    asm("add.rn.f32x2 %0, %1, %2;" : "=l"(a) : "l"(a), "l"(b));
}
__device__ __forceinline__ u64 pack2(float a, float b) {
    u64 r; asm("mov.b64 %0, {%1, %2};" : "=l"(r) : "f"(a), "f"(b)); return r;
}
__device__ __forceinline__ float lo_f(u64 v) { return __uint_as_float((unsigned)v); }
__device__ __forceinline__ float hi_f(u64 v) { return __uint_as_float((unsigned)(v >> 32)); }
__device__ __forceinline__ float hsum(u64 v) { return lo_f(v) + hi_f(v); }
__device__ __forceinline__ float tanh_ap(float x) {
    float y; asm("tanh.approx.f32 %0, %1;" : "=f"(y) : "f"(x)); return y;
}
__device__ __forceinline__ float sigm(float x) {
    return fmaf(0.5f, tanh_ap(0.5f * x), 0.5f);
}
__device__ __forceinline__ u64 shflx(u64 v, int mask) {
    unsigned lo = (unsigned)v, hi = (unsigned)(v >> 32);
    lo = __shfl_xor_sync(0xffffffffu, lo, mask);
    hi = __shfl_xor_sync(0xffffffffu, hi, mask);
    return ((u64)hi << 32) | lo;
}

__device__ __forceinline__ float xin_value(const float* trajs, const float* preds,
                                           int w, int s, int f) {
    if (w == 0) return trajs[s * 4 + f];
    if (w < WS) {
        if (s < WS - w) return trajs[(w + s) * 4 + f];
        return (f < 2) ? trajs[(2 * w + s - 1) * 4 + f]
                       : preds[(w + s - WS) * 2 + (f - 2)];
    }
    return (f < 2) ? trajs[(w + s) * 4 + f]
                   : preds[(w + s - WS) * 2 + (f - 2)];
}

__global__ __launch_bounds__(384, 1)
void or_lstm_kernel(const float* __restrict__ traj,
                    const float* __restrict__ Wih0, const float* __restrict__ Whh0,
                    const float* __restrict__ bih0, const float* __restrict__ bhh0,
                    const float* __restrict__ Wih1, const float* __restrict__ Whh1,
                    const float* __restrict__ bih1, const float* __restrict__ bhh1,
                    const float* __restrict__ Wlin, const float* __restrict__ blin,
                    float* __restrict__ out)
{
    const int b   = blockIdx.x;
    const int tid = threadIdx.x;

    __shared__ __align__(16) float trajs[TT * 4];
    __shared__ __align__(16) float hbuf[2][2][HH];   // [layer][parity][h]
    __shared__ __align__(16) float xin[2][WS][4];    // [window parity][step][feat]
    __shared__ float preds[NW * 2];
    __shared__ float predpart[16];                   // 8 L1 warps x 2 rows
    __shared__ float blin_s[2];

    for (int i = tid; i < TT * 4; i += 384) trajs[i] = traj[b * TT * 4 + i];
    if (tid < 2) blin_s[tid] = blin[tid];

    const bool isL0 = tid < 128;
    const int  m0 = tid >> 1,        sl0 = tid & 1;       // L0: 64 groups x 2 slices
    const int  t1 = tid - 128;
    const int  m1 = t1 >> 2,         sl1 = t1 & 3;        // L1: 64 groups x 4 slices

    // ---- weights -> registers ----
    u64 wreg[4][16];     // per gate: 32 k-values (16 packed pairs)
    u64 wx[4];           // L0 only: 2 x-features per gate
    u64 bp0, bp1;        // packed biases (gates 0,1) and (2,3)
    float wl = 0.0f;     // L1 only: Wlin element

    if (isL0) {
        float bb[4];
        #pragma unroll
        for (int g = 0; g < 4; g++) {
            const int rg = 64 * g + m0;
            const ulonglong2* src = (const ulonglong2*)(Whh0 + rg * HH + 32 * sl0);
            #pragma unroll
            for (int c = 0; c < 8; c++) {
                ulonglong2 v = src[c];
                wreg[g][2 * c] = v.x; wreg[g][2 * c + 1] = v.y;
            }
            wx[g] = pack2(Wih0[rg * 4 + 2 * sl0], Wih0[rg * 4 + 2 * sl0 + 1]);
            bb[g] = bih0[rg] + bhh0[rg];
        }
        bp0 = pack2(bb[0], bb[1]); bp1 = pack2(bb[2], bb[3]);
    } else {
        float bb[4];
        #pragma unroll
        for (int g = 0; g < 4; g++) {
            const int rg = 64 * g + m1;
            const float* srcf = (sl1 < 2) ? (Wih1 + rg * HH + 32 * sl1)
                                          : (Whh1 + rg * HH + 32 * (sl1 - 2));
            const ulonglong2* src = (const ulonglong2*)srcf;
            #pragma unroll
            for (int c = 0; c < 8; c++) {
                ulonglong2 v = src[c];
                wreg[g][2 * c] = v.x; wreg[g][2 * c + 1] = v.y;
            }
            bb[g] = bih1[rg] + bhh1[rg];
            wx[g] = 0;
        }
        bp0 = pack2(bb[0], bb[1]); bp1 = pack2(bb[2], bb[3]);
        wl = (sl1 < 2) ? Wlin[sl1 * 64 + m1] : 0.0f;
    }

    float cst = 0.0f, hv = 0.0f;   // this engine's cell & hidden state

    __syncthreads();                        // trajs staged
    if (tid < 32) {                         // prebuild xin window 0 (pure traj)
        const int s = tid >> 2, f = tid & 3;
        xin[0][s][f] = trajs[s * 4 + f];
    }
    __syncthreads();

    for (int g = 0; g < NP; g++) {
        const int w0 = g >> 3, s0 = g & 7;
        const int pw = g & 1, pr = pw ^ 1;

        if (isL0) {
            // ================= layer-0 engine: h0(w0, s0) =================
            if (w0 < NW) {
                u64 a0, a1, a2, a3;
                {
                    u64 xx = *(const u64*)&xin[w0 & 1][s0][2 * sl0];
                    a0 = 0; a1 = 0; a2 = 0; a3 = 0;
                    fma2(a0, xx, wx[0]); fma2(a1, xx, wx[1]);
                    fma2(a2, xx, wx[2]); fma2(a3, xx, wx[3]);
                }
                if (s0 > 0) {
                    const ulonglong2* hp = (const ulonglong2*)&hbuf[0][pr][32 * sl0];
                    #pragma unroll
                    for (int c = 0; c < 8; c++) {
                        ulonglong2 h2 = hp[c];
                        fma2(a0, h2.x, wreg[0][2 * c]); fma2(a0, h2.y, wreg[0][2 * c + 1]);
                        fma2(a1, h2.x, wreg[1][2 * c]); fma2(a1, h2.y, wreg[1][2 * c + 1]);
                        fma2(a2, h2.x, wreg[2][2 * c]); fma2(a2, h2.y, wreg[2][2 * c + 1]);
                        fma2(a3, h2.x, wreg[3][2 * c]); fma2(a3, h2.y, wreg[3][2 * c + 1]);
                    }
                }
                u64 A = pack2(hsum(a0), hsum(a1));
                u64 B = pack2(hsum(a2), hsum(a3));
                add2(A, shflx(A, 1)); add2(B, shflx(B, 1));
                add2(A, bp0);         add2(B, bp1);
                float ig = sigm(lo_f(A)), fg = sigm(hi_f(A));
                float gg = tanh_ap(lo_f(B)), og = sigm(hi_f(B));
                cst = (s0 == 0) ? ig * gg : fmaf(fg, cst, ig * gg);
                hv  = og * tanh_ap(cst);
                if (sl0 == 0) hbuf[0][pw][m0] = hv;
            }
            // --- side task: finalize pred[w0-1] (partials written last phase) ---
            if (s0 == 1 && w0 >= 1 && tid < 2) {
                const int w = w0 - 1;
                float d = blin_s[tid];
                #pragma unroll
                for (int k = 0; k < 8; k++) d += predpart[k * 2 + tid];
                const float prev = (w == 0) ? trajs[7 * 4 + 2 + tid]
                                            : preds[(w - 1) * 2 + tid];
                const float p = prev + d;
                preds[w * 2 + tid] = p;
                out[(b * NW + w) * 2 + tid] = p;
            }
            // --- side task: build xin rows (all needed preds already final) ---
            if (s0 == 2 && w0 < NW) {
                if (tid >= 2 && tid < 30 && (w0 + 1) < NW) {   // rows 0..6 of w0+1
                    const int idx = tid - 2, s = idx >> 2, f = idx & 3;
                    xin[(w0 + 1) & 1][s][f] = xin_value(trajs, preds, w0 + 1, s, f);
                }
                if (tid >= 30 && tid < 34) {                   // row 7 of w0
                    const int f = tid - 30;
                    xin[w0 & 1][7][f] = xin_value(trajs, preds, w0, 7, f);
                }
            }
        } else {
            // ================= layer-1 engine: h1(w1, s1), one phase behind ====
            const int g1 = g - 1;
            if (g1 >= 0 && g1 < NW * 8) {
                const int s1 = g1 & 7;
                u64 a0 = 0, a1 = 0, a2 = 0, a3 = 0;
                if (sl1 < 2 || s1 > 0) {
                    const float* hsrc = (sl1 < 2) ? &hbuf[0][pr][32 * sl1]
                                                  : &hbuf[1][pr][32 * (sl1 - 2)];
                    const ulonglong2* hp = (const ulonglong2*)hsrc;
                    #pragma unroll
                    for (int c = 0; c < 8; c++) {
                        ulonglong2 h2 = hp[c];
                        fma2(a0, h2.x, wreg[0][2 * c]); fma2(a0, h2.y, wreg[0][2 * c + 1]);
                        fma2(a1, h2.x, wreg[1][2 * c]); fma2(a1, h2.y, wreg[1][2 * c + 1]);
                        fma2(a2, h2.x, wreg[2][2 * c]); fma2(a2, h2.y, wreg[2][2 * c + 1]);
                        fma2(a3, h2.x, wreg[3][2 * c]); fma2(a3, h2.y, wreg[3][2 * c + 1]);
                    }
                }
                u64 A = pack2(hsum(a0), hsum(a1));
                u64 B = pack2(hsum(a2), hsum(a3));
                add2(A, shflx(A, 1)); add2(B, shflx(B, 1));
                add2(A, shflx(A, 2)); add2(B, shflx(B, 2));
                add2(A, bp0);         add2(B, bp1);
                float ig = sigm(lo_f(A)), fg = sigm(hi_f(A));
                float gg = tanh_ap(lo_f(B)), og = sigm(hi_f(B));
                cst = (s1 == 0) ? ig * gg : fmaf(fg, cst, ig * gg);
                hv  = og * tanh_ap(cst);
                if (sl1 == 0) hbuf[1][pw][m1] = hv;
                if (s1 == 7) {   // in-warp partial of Wlin . h1(w,7)
                    float pv = wl * hv;
                    pv += __shfl_xor_sync(0xffffffffu, pv, 4);
                    pv += __shfl_xor_sync(0xffffffffu, pv, 8);
                    pv += __shfl_xor_sync(0xffffffffu, pv, 16);
                    if ((t1 & 31) < 2) predpart[(t1 >> 5) * 2 + (t1 & 31)] = pv;
                }
            }
        }
        __syncthreads();
    }

    // ---- final states: h[2,B,H] then c[2,B,H] (regs hold window-247 values) ----
    const int base = BB * NW * 2;
    if (isL0) {
        if (sl0 == 0) {
            out[base + 0 * BB * HH + b * HH + m0] = hv;
            out[base + 2 * BB * HH + b * HH + m0] = cst;
        }
    } else {
        if (sl1 == 0) {
            out[base + 1 * BB * HH + b * HH + m1] = hv;
            out[base + 3 * BB * HH + b * HH + m1] = cst;
        }
    }
}

extern "C" void kernel_launch(void* const* d_in, const int* in_sizes, int n_in,
                              void* d_out, int out_size) {
    const float* traj = (const float*)d_in[0];
    const float* Wih0 = (const float*)d_in[1];
    const float* Whh0 = (const float*)d_in[2];
    const float* bih0 = (const float*)d_in[3];
    const float* bhh0 = (const float*)d_in[4];
    const float* Wih1 = (const float*)d_in[5];
    const float* Whh1 = (const float*)d_in[6];
    const float* bih1 = (const float*)d_in[7];
    const float* bhh1 = (const float*)d_in[8];
    const float* Wlin = (const float*)d_in[9];
    const float* blin = (const float*)d_in[10];

    or_lstm_kernel<<<BB, 384>>>(traj, Wih0, Whh0, bih0, bhh0,
                                Wih1, Whh1, bih1, bhh1,
                                Wlin, blin, (float*)d_out);
}